// round 3
// baseline (speedup 1.0000x reference)
#include <cuda_runtime.h>
#include <cstdint>

#define THREADS   256
#define ITEMS     8
#define TILE      (THREADS * ITEMS)   // 2048
#define NT_MAX    16384
#define FULLMASK  0xFFFFFFFFu
#define DISC      0.99f

// ---- cross-block decoupled-lookback state (static __device__: no allocs) ----
__device__ unsigned g_gen = 0;
__device__ unsigned g_flag[NT_MAX];   // gen*4 + {1=partial, 2=inclusive}
__device__ float    g_pA[NT_MAX];
__device__ float    g_pB[NT_MAX];
__device__ float    g_pY[NT_MAX];

__global__ void init_k() { g_gen += 1u; }

__device__ __forceinline__ void st_release(unsigned* p, unsigned v) {
    asm volatile("st.release.gpu.global.u32 [%0], %1;" :: "l"(p), "r"(v) : "memory");
}
__device__ __forceinline__ unsigned ld_acquire(const unsigned* p) {
    unsigned v;
    asm volatile("ld.acquire.gpu.global.u32 %0, [%1];" : "=r"(v) : "l"(p) : "memory");
    return v;
}

// y[t] = a[t]*y[t+1] + r[t],  a = terminal[t] ? 0 : DISC,  y[n] = 0 (FINAL_REWARD=0)
// Tile j covers [n-(j+1)*TILE, n-j*TILE): tile 0 = rightmost -> carry-in 0.
__global__ void __launch_bounds__(THREADS, 6)
scan_k(const float* __restrict__ reward,
       const int* __restrict__ term,       // bool materialized as int32 (0/1)
       float* __restrict__ out, int n)
{
    __shared__ float s_wA[8], s_wB[8];
    __shared__ float s_Yin;

    const int t = threadIdx.x;
    const unsigned tile = blockIdx.x;
    const unsigned gen4 = g_gen * 4u;
    const int lane = t & 31;
    const int wid  = t >> 5;

    const long long base = (long long)n - (long long)(tile + 1) * TILE;
    const long long cs   = base + (long long)t * ITEMS;   // this thread's chunk start
    const bool full = (base >= 0);

    float r[ITEMS];
    unsigned tmask = 0u;   // bit i: terminal at item i  -> a = 0
    unsigned onemask = 0u; // bit i: padding item        -> a = 1, r = 0

    if (full) {
        const float4* rp = (const float4*)(reward + cs);
        float4 v0 = rp[0], v1 = rp[1];
        r[0]=v0.x; r[1]=v0.y; r[2]=v0.z; r[3]=v0.w;
        r[4]=v1.x; r[5]=v1.y; r[6]=v1.z; r[7]=v1.w;
        const int4* tp = (const int4*)(term + cs);
        int4 w0 = tp[0], w1 = tp[1];
        int tv[ITEMS] = { w0.x,w0.y,w0.z,w0.w, w1.x,w1.y,w1.z,w1.w };
        #pragma unroll
        for (int i = 0; i < ITEMS; ++i)
            if (tv[i] != 0) tmask |= (1u << i);
    } else {
        // ragged tail tile (not hit when n % TILE == 0, kept for generality)
        #pragma unroll
        for (int i = 0; i < ITEMS; ++i) {
            long long g = cs + i;
            if (g >= 0 && g < (long long)n) {
                r[i] = reward[g];
                if (term[g] != 0) tmask |= (1u << i);
            } else {
                r[i] = 0.0f;
                onemask |= (1u << i);   // identity element
            }
        }
    }

    // ---- per-thread chunk affine: (A, B) maps y[chunk_end+1] -> y[chunk_start]
    float A = 1.0f, B = 0.0f;
    {
        float y = 0.0f;
        #pragma unroll
        for (int i = ITEMS - 1; i >= 0; --i) {
            float a = ((tmask >> i) & 1u) ? 0.0f : (((onemask >> i) & 1u) ? 1.0f : DISC);
            y = fmaf(a, y, r[i]);
            A *= a;
        }
        B = y;
    }

    // ---- warp suffix scan (lane k -> composition of lanes k..31, self-after-right)
    float Ai = A, Bi = B;
    #pragma unroll
    for (int d = 1; d < 32; d <<= 1) {
        float a2 = __shfl_down_sync(FULLMASK, Ai, d);
        float b2 = __shfl_down_sync(FULLMASK, Bi, d);
        if (lane + d < 32) { Bi = fmaf(Ai, b2, Bi); Ai = Ai * a2; }
    }
    // exclusive within warp = inclusive of lane+1
    float exA = __shfl_down_sync(FULLMASK, Ai, 1);
    float exB = __shfl_down_sync(FULLMASK, Bi, 1);
    if (lane == 31) { exA = 1.0f; exB = 0.0f; }

    if (lane == 0) { s_wA[wid] = Ai; s_wB[wid] = Bi; }
    __syncthreads();

    // carry affine for this warp = composition of warps wid+1..7 (outer->inner)
    float cA = 1.0f, cB = 0.0f;
    #pragma unroll
    for (int w = 0; w < 8; ++w) {
        if (w > wid) {
            cB = fmaf(cA, s_wB[w], cB);
            cA = cA * s_wA[w];
        }
    }
    // total exclusive affine for this thread: maps tile carry -> this chunk's carry
    const float etA = exA * cA;
    const float etB = fmaf(exA, cB, exB);

    // ---- publish + decoupled lookback (warp 0 only)
    if (wid == 0) {
        // lane 0 holds tile aggregate = incl(warp0) ∘ C_0
        float At = Ai * cA;
        float Bt = fmaf(Ai, cB, Bi);

        if (tile == 0) {
            if (lane == 0) {
                __stcg(&g_pY[0], Bt);           // carry-in is 0 -> Y = B
                st_release(&g_flag[0], gen4 + 2u);
                s_Yin = 0.0f;
            }
        } else {
            if (lane == 0) {
                __stcg(&g_pA[tile], At);
                __stcg(&g_pB[tile], Bt);
                st_release(&g_flag[tile], gen4 + 1u);
            }
            float oA = 1.0f, oB = 0.0f;   // meaningful on lane 0 only
            int idx0 = (int)tile - 1;
            float yin = 0.0f;
            while (true) {
                int i = idx0 - lane;
                bool pend = (i >= 0);
                unsigned f = 0u;
                if (pend) {
                    f = ld_acquire(&g_flag[i]);
                    unsigned backoff = 20u;
                    while (f <= gen4) {                    // not yet published this gen
                        __nanosleep(backoff);
                        if (backoff < 200u) backoff <<= 1;
                        f = ld_acquire(&g_flag[i]);
                    }
                }
                float pA, pB;
                if (!pend)                { pA = 1.0f; pB = 0.0f; }
                else if (f == gen4 + 2u)  { pA = 0.0f; pB = __ldcg(&g_pY[i]); }  // constant affine
                else                      { pA = __ldcg(&g_pA[i]); pB = __ldcg(&g_pB[i]); }
                // ordered composition: lane0 gets f(i0) ∘ f(i0-1) ∘ ... ∘ f(i0-31)
                #pragma unroll
                for (int d = 1; d < 32; d <<= 1) {
                    float a2 = __shfl_down_sync(FULLMASK, pA, d);
                    float b2 = __shfl_down_sync(FULLMASK, pB, d);
                    if (lane + d < 32) { pB = fmaf(pA, b2, pB); pA = pA * a2; }
                }
                float ncA = 0.0f, ncB = 0.0f;
                if (lane == 0) { ncB = fmaf(oA, pB, oB); ncA = oA * pA; }
                ncA = __shfl_sync(FULLMASK, ncA, 0);
                ncB = __shfl_sync(FULLMASK, ncB, 0);
                if (fabsf(ncA) < 1e-30f) { yin = ncB; break; }   // exact (underflow) truncation
                oA = ncA; oB = ncB;
                idx0 -= 32;
            }
            if (lane == 0) {
                float Yt = fmaf(At, yin, Bt);
                __stcg(&g_pY[tile], Yt);
                st_release(&g_flag[tile], gen4 + 2u);
                s_Yin = yin;
            }
        }
    }
    __syncthreads();
    const float Yin = s_Yin;

    // ---- produce outputs
    float y = fmaf(etA, Yin, etB);   // carry entering this chunk from the right
    #pragma unroll
    for (int i = ITEMS - 1; i >= 0; --i) {
        float a = ((tmask >> i) & 1u) ? 0.0f : (((onemask >> i) & 1u) ? 1.0f : DISC);
        y = fmaf(a, y, r[i]);
        r[i] = y;
    }
    if (full) {
        float4* op = (float4*)(out + cs);
        op[0] = make_float4(r[0], r[1], r[2], r[3]);
        op[1] = make_float4(r[4], r[5], r[6], r[7]);
    } else {
        #pragma unroll
        for (int i = 0; i < ITEMS; ++i) {
            long long g = cs + i;
            if (g >= 0 && g < (long long)n) out[g] = r[i];
        }
    }
}

extern "C" void kernel_launch(void* const* d_in, const int* in_sizes, int n_in,
                              void* d_out, int out_size)
{
    const int*   term   = (const int*)d_in[0];     // 'terminal' (bool -> int32)
    const float* reward = (const float*)d_in[1];   // 'reward' (f32)
    float*       out    = (float*)d_out;
    int n  = in_sizes[1];
    int nt = (n + TILE - 1) / TILE;
    if (nt > NT_MAX) nt = NT_MAX;  // T=16777216 -> nt=8192

    init_k<<<1, 1>>>();
    scan_k<<<nt, THREADS>>>(reward, term, out, n);
}

// round 4
// speedup vs baseline: 2.5837x; 2.5837x over previous
#include <cuda_runtime.h>
#include <cstdint>

#define THREADS  512
#define ITEMS    16
#define TILE     (THREADS * ITEMS)    // 8192
#define HALO     2048
#define HITEMS   (HALO / THREADS)     // 4
#define NWARPS   (THREADS / 32)       // 16
#define FULLMASK 0xFFFFFFFFu
#define DISC     0.99f

// y[t] = a[t]*y[t+1] + r[t],  a = terminal[t] ? 0 : DISC,  y[n] = 0 (FINAL_REWARD=0).
// Halo truncation: carry into a tile via 2048 non-terminal steps is scaled by
// 0.99^2048 = 1.15e-9 -> below fp32 noise; any terminal in the halo makes it exact.
// => blocks are fully independent. No flags, no atomics, no lookback.
__global__ void __launch_bounds__(THREADS, 2)
scan_k(const float* __restrict__ reward,
       const int*  __restrict__ term,      // bool materialized as int32 (0/1)
       float*      __restrict__ out, int n)
{
    __shared__ float s_hA[NWARPS], s_hB[NWARPS];   // halo warp aggregates
    __shared__ float s_wA[NWARPS], s_wB[NWARPS];   // owned warp aggregates

    const int t    = threadIdx.x;
    const int lane = t & 31;
    const int wid  = t >> 5;

    const long long s  = (long long)blockIdx.x * TILE;
    const long long cs = s + (long long)t * ITEMS;           // owned chunk start
    const long long hs = s + TILE + (long long)t * HITEMS;   // halo chunk start

    const bool ownFull = (s + TILE        <= (long long)n);
    const bool extFull = (s + TILE + HALO <= (long long)n);

    // ---------------- loads (everything issued up front for MLP) ----------------
    float    r[ITEMS];
    unsigned tmask = 0u, onemask = 0u;      // owned: terminal bits / padding bits
    float    hr[HITEMS];
    unsigned htmask = 0u, honemask = 0u;    // halo

    if (ownFull) {
        const float4* rp = (const float4*)(reward + cs);
        const int4*   tp = (const int4*)(term + cs);
        float4 v0 = rp[0], v1 = rp[1], v2 = rp[2], v3 = rp[3];
        int4   w0 = tp[0], w1 = tp[1], w2 = tp[2], w3 = tp[3];
        r[0]=v0.x; r[1]=v0.y; r[2]=v0.z; r[3]=v0.w;
        r[4]=v1.x; r[5]=v1.y; r[6]=v1.z; r[7]=v1.w;
        r[8]=v2.x; r[9]=v2.y; r[10]=v2.z; r[11]=v2.w;
        r[12]=v3.x; r[13]=v3.y; r[14]=v3.z; r[15]=v3.w;
        int tv[ITEMS] = { w0.x,w0.y,w0.z,w0.w, w1.x,w1.y,w1.z,w1.w,
                          w2.x,w2.y,w2.z,w2.w, w3.x,w3.y,w3.z,w3.w };
        #pragma unroll
        for (int i = 0; i < ITEMS; ++i)
            if (tv[i] != 0) tmask |= (1u << i);
    } else {
        #pragma unroll
        for (int i = 0; i < ITEMS; ++i) {
            long long g = cs + i;
            if (g < (long long)n) {
                r[i] = reward[g];
                if (term[g] != 0) tmask |= (1u << i);
            } else { r[i] = 0.0f; onemask |= (1u << i); }   // identity element
        }
    }

    if (extFull) {
        float4 hv = *(const float4*)(reward + hs);
        int4   hw = *(const int4*)(term + hs);
        hr[0]=hv.x; hr[1]=hv.y; hr[2]=hv.z; hr[3]=hv.w;
        int htv[HITEMS] = { hw.x, hw.y, hw.z, hw.w };
        #pragma unroll
        for (int i = 0; i < HITEMS; ++i)
            if (htv[i] != 0) htmask |= (1u << i);
    } else {
        #pragma unroll
        for (int i = 0; i < HITEMS; ++i) {
            long long g = hs + i;
            if (g < (long long)n) {
                hr[i] = reward[g];
                if (term[g] != 0) htmask |= (1u << i);
            } else { hr[i] = 0.0f; honemask |= (1u << i); }
        }
    }

    // ---------------- halo: per-thread affine, then warp suffix-compose ----------
    float hA = 1.0f, hB;
    {
        float y = 0.0f;
        #pragma unroll
        for (int i = HITEMS - 1; i >= 0; --i) {
            float a = ((htmask >> i) & 1u) ? 0.0f : (((honemask >> i) & 1u) ? 1.0f : DISC);
            y = fmaf(a, y, hr[i]);
            hA *= a;
        }
        hB = y;
    }
    #pragma unroll
    for (int d = 1; d < 32; d <<= 1) {
        float a2 = __shfl_down_sync(FULLMASK, hA, d);
        float b2 = __shfl_down_sync(FULLMASK, hB, d);
        if (lane + d < 32) { hB = fmaf(hA, b2, hB); hA = hA * a2; }
    }

    // ---------------- owned: per-thread affine + warp suffix scan ----------------
    float A = 1.0f, B;
    {
        float y = 0.0f;
        #pragma unroll
        for (int i = ITEMS - 1; i >= 0; --i) {
            float a = ((tmask >> i) & 1u) ? 0.0f : (((onemask >> i) & 1u) ? 1.0f : DISC);
            y = fmaf(a, y, r[i]);
            A *= a;
        }
        B = y;
    }
    float Ai = A, Bi = B;
    #pragma unroll
    for (int d = 1; d < 32; d <<= 1) {
        float a2 = __shfl_down_sync(FULLMASK, Ai, d);
        float b2 = __shfl_down_sync(FULLMASK, Bi, d);
        if (lane + d < 32) { Bi = fmaf(Ai, b2, Bi); Ai = Ai * a2; }
    }
    float exA = __shfl_down_sync(FULLMASK, Ai, 1);     // exclusive = inclusive of lane+1
    float exB = __shfl_down_sync(FULLMASK, Bi, 1);
    if (lane == 31) { exA = 1.0f; exB = 0.0f; }

    if (lane == 0) {
        s_hA[wid] = hA; s_hB[wid] = hB;    // halo warp total (lane 0 of suffix scan)
        s_wA[wid] = Ai; s_wB[wid] = Bi;    // owned warp total
    }
    __syncthreads();

    // yin: halo composition applied to 0, Horner over warp aggregates (right->left)
    float yin = 0.0f;
    #pragma unroll
    for (int w = NWARPS - 1; w >= 0; --w)
        yin = fmaf(s_hA[w], yin, s_hB[w]);

    // carry affine for this warp = composition of owned warps wid+1..15
    float cA = 1.0f, cB = 0.0f;
    #pragma unroll
    for (int w = 0; w < NWARPS; ++w) {
        if (w > wid) {
            cB = fmaf(cA, s_wB[w], cB);
            cA = cA * s_wA[w];
        }
    }
    const float etA = exA * cA;
    const float etB = fmaf(exA, cB, exB);

    // ---------------- outputs ----------------
    float y = fmaf(etA, yin, etB);    // carry entering this thread's chunk
    #pragma unroll
    for (int i = ITEMS - 1; i >= 0; --i) {
        float a = ((tmask >> i) & 1u) ? 0.0f : (((onemask >> i) & 1u) ? 1.0f : DISC);
        y = fmaf(a, y, r[i]);
        r[i] = y;
    }
    if (ownFull) {
        float4* op = (float4*)(out + cs);
        __stcs(op + 0, make_float4(r[0],  r[1],  r[2],  r[3]));
        __stcs(op + 1, make_float4(r[4],  r[5],  r[6],  r[7]));
        __stcs(op + 2, make_float4(r[8],  r[9],  r[10], r[11]));
        __stcs(op + 3, make_float4(r[12], r[13], r[14], r[15]));
    } else {
        #pragma unroll
        for (int i = 0; i < ITEMS; ++i) {
            long long g = cs + i;
            if (g < (long long)n) out[g] = r[i];
        }
    }
}

extern "C" void kernel_launch(void* const* d_in, const int* in_sizes, int n_in,
                              void* d_out, int out_size)
{
    const int*   term   = (const int*)d_in[0];     // 'terminal' (bool -> int32)
    const float* reward = (const float*)d_in[1];   // 'reward' (f32)
    float*       out    = (float*)d_out;
    int n  = in_sizes[1];
    int nb = (n + TILE - 1) / TILE;                // 2048 for T=16777216
    scan_k<<<nb, THREADS>>>(reward, term, out, n);
}